// round 1
// baseline (speedup 1.0000x reference)
#include <cuda_runtime.h>
#include <math.h>

// Problem constants: B=4, S=2048, D=1024, H=4, HD=256, R=B*S=8192
#define R_ROWS 8192
#define DIM    1024
#define NHEAD  4
#define HDIM   256

// Scratch (no allocation allowed -> __device__ globals)
__device__ float g_Q[8388608];
__device__ float g_K[8388608];
__device__ float g_V[8388608];
__device__ float g_ATTN[8388608];
__device__ float g_NUM[8388608];
__device__ float g_DENQ[32768];
__device__ float g_DENK[32768];

__device__ __forceinline__ float elu1(float x) { return x > 0.f ? x + 1.f : __expf(x); }

#define FMA16(av, bv) \
  acc[0][0]+=av.x*bv.x; acc[0][1]+=av.x*bv.y; acc[0][2]+=av.x*bv.z; acc[0][3]+=av.x*bv.w; \
  acc[1][0]+=av.y*bv.x; acc[1][1]+=av.y*bv.y; acc[1][2]+=av.y*bv.z; acc[1][3]+=av.y*bv.w; \
  acc[2][0]+=av.z*bv.x; acc[2][1]+=av.z*bv.y; acc[2][2]+=av.z*bv.z; acc[2][3]+=av.z*bv.w; \
  acc[3][0]+=av.w*bv.x; acc[3][1]+=av.w*bv.y; acc[3][2]+=av.w*bv.z; acc[3][3]+=av.w*bv.w;

// ---------------------------------------------------------------------------
// C[M,N] = A[M,K] @ B[N,K]^T (+bias). 64x64 tile, BK=16, 4x4 per thread.
// ---------------------------------------------------------------------------
__global__ void __launch_bounds__(256) gemm_tn(const float* __restrict__ A,
    const float* __restrict__ Bm, const float* __restrict__ bias,
    float* __restrict__ C, int M, int N, int Kd) {
  __shared__ float As[16][64];
  __shared__ float Bs[16][64];
  int tid = threadIdx.x;
  int m0 = blockIdx.y * 64, n0 = blockIdx.x * 64;
  int i0 = (tid >> 4) << 2, j0 = (tid & 15) << 2;
  int lr = tid >> 2, lk = (tid & 3) << 2;
  float acc[4][4] = {};
  for (int k0 = 0; k0 < Kd; k0 += 16) {
    float4 a = *(const float4*)&A[(size_t)(m0 + lr) * Kd + k0 + lk];
    float4 b = *(const float4*)&Bm[(size_t)(n0 + lr) * Kd + k0 + lk];
    __syncthreads();
    As[lk+0][lr]=a.x; As[lk+1][lr]=a.y; As[lk+2][lr]=a.z; As[lk+3][lr]=a.w;
    Bs[lk+0][lr]=b.x; Bs[lk+1][lr]=b.y; Bs[lk+2][lr]=b.z; Bs[lk+3][lr]=b.w;
    __syncthreads();
#pragma unroll
    for (int kk = 0; kk < 16; kk++) {
      float4 av = *(const float4*)&As[kk][i0];
      float4 bv = *(const float4*)&Bs[kk][j0];
      FMA16(av, bv)
    }
  }
#pragma unroll
  for (int ii = 0; ii < 4; ii++) {
    float4 r = make_float4(acc[ii][0], acc[ii][1], acc[ii][2], acc[ii][3]);
    if (bias) {
      float4 bb = *(const float4*)&bias[n0 + j0];
      r.x += bb.x; r.y += bb.y; r.z += bb.z; r.w += bb.w;
    }
    *(float4*)&C[(size_t)(m0 + i0 + ii) * N + n0 + j0] = r;
  }
}

// ---------------------------------------------------------------------------
// NUM[r][h*256+n] = sum_d elu1(X[r][h*256+d]) * Mem[h][d][n]   (K=256)
// grid (4 n-tiles, 128 m-tiles, 4 heads)
// ---------------------------------------------------------------------------
__global__ void __launch_bounds__(256) gemm_nn_elu(const float* __restrict__ X,
    const float* __restrict__ Mem, float* __restrict__ C) {
  __shared__ float As[16][64];
  __shared__ float Bs[16][64];
  int tid = threadIdx.x;
  int h = blockIdx.z;
  int m0 = blockIdx.y * 64, n0 = blockIdx.x * 64;
  int i0 = (tid >> 4) << 2, j0 = (tid & 15) << 2;
  int lr = tid >> 2, lk = (tid & 3) << 2;
  int br = tid >> 4, bc = (tid & 15) << 2;
  const float* Mh = Mem + (size_t)h * 65536;
  float acc[4][4] = {};
  for (int k0 = 0; k0 < 256; k0 += 16) {
    float4 a = *(const float4*)&X[(size_t)(m0 + lr) * DIM + h * HDIM + k0 + lk];
    float4 b = *(const float4*)&Mh[(size_t)(k0 + br) * HDIM + n0 + bc];
    __syncthreads();
    As[lk+0][lr]=elu1(a.x); As[lk+1][lr]=elu1(a.y); As[lk+2][lr]=elu1(a.z); As[lk+3][lr]=elu1(a.w);
    *(float4*)&Bs[br][bc] = b;
    __syncthreads();
#pragma unroll
    for (int kk = 0; kk < 16; kk++) {
      float4 av = *(const float4*)&As[kk][i0];
      float4 bv = *(const float4*)&Bs[kk][j0];
      FMA16(av, bv)
    }
  }
#pragma unroll
  for (int ii = 0; ii < 4; ii++) {
    float4 r = make_float4(acc[ii][0], acc[ii][1], acc[ii][2], acc[ii][3]);
    *(float4*)&C[(size_t)(m0 + i0 + ii) * DIM + h * HDIM + n0 + j0] = r;
  }
}

// ---------------------------------------------------------------------------
// mem_new[h][d][e] = mem[h][d][e] + 0.25 * sum_r elu1(K[r][h*256+d]) * U[r][h*256+e]
// grid (4 e-tiles, 4 d-tiles, 4 heads); K-loop over 8192 rows.
// ---------------------------------------------------------------------------
__global__ void __launch_bounds__(256) gemm_atb(const float* __restrict__ Kb,
    const float* __restrict__ U, const float* __restrict__ Memin,
    float* __restrict__ Out) {
  __shared__ float As[16][64];
  __shared__ float Bs[16][64];
  int tid = threadIdx.x;
  int h = blockIdx.z;
  int d0 = blockIdx.y * 64, e0 = blockIdx.x * 64;
  int i0 = (tid >> 4) << 2, j0 = (tid & 15) << 2;
  int br = tid >> 4, bc = (tid & 15) << 2;
  float acc[4][4] = {};
  for (int r0 = 0; r0 < R_ROWS; r0 += 16) {
    float4 a = *(const float4*)&Kb[(size_t)(r0 + br) * DIM + h * HDIM + d0 + bc];
    float4 b = *(const float4*)&U[(size_t)(r0 + br) * DIM + h * HDIM + e0 + bc];
    __syncthreads();
    As[br][bc+0]=elu1(a.x); As[br][bc+1]=elu1(a.y); As[br][bc+2]=elu1(a.z); As[br][bc+3]=elu1(a.w);
    *(float4*)&Bs[br][bc] = b;
    __syncthreads();
#pragma unroll
    for (int kk = 0; kk < 16; kk++) {
      float4 av = *(const float4*)&As[kk][i0];
      float4 bv = *(const float4*)&Bs[kk][j0];
      FMA16(av, bv)
    }
  }
#pragma unroll
  for (int ii = 0; ii < 4; ii++) {
    size_t idx = (size_t)h * 65536 + (size_t)(d0 + i0 + ii) * HDIM + e0 + j0;
    float4 m = *(const float4*)&Memin[idx];
    float4 r = make_float4(m.x + 0.25f*acc[ii][0], m.y + 0.25f*acc[ii][1],
                           m.z + 0.25f*acc[ii][2], m.w + 0.25f*acc[ii][3]);
    *(float4*)&Out[idx] = r;
  }
}

// ---------------------------------------------------------------------------
// Flash attention (causal, no scaling). grid(32 q-tiles, 16 b*h), 256 threads.
// Q/K in smem transposed [256][64]; V natural [64][256]; O column-per-thread.
// ---------------------------------------------------------------------------
#define FL_SMEM ((16384*3 + 4096 + 192) * 4)

__global__ void __launch_bounds__(256) flash_kernel(const float* __restrict__ Q,
    const float* __restrict__ Kb, const float* __restrict__ V,
    float* __restrict__ O) {
  extern __shared__ float sm[];
  float* Qs = sm;            // [256][64]
  float* Ks = sm + 16384;    // [256][64]
  float* Vs = sm + 32768;    // [64][256]
  float* Ps = sm + 49152;    // [64][64]
  float* Ms = sm + 53248;    // [64]
  float* Ls = sm + 53312;    // [64]
  float* Ss = sm + 53376;    // [64]
  int tid = threadIdx.x;
  int b = blockIdx.y >> 2, h = blockIdx.y & 3;
  size_t base = (size_t)b * (2048 * 1024) + h * HDIM;
  int q0 = blockIdx.x * 64;

#pragma unroll
  for (int rep = 0; rep < 16; rep++) {
    int e = rep * 1024 + tid * 4;
    int row = e >> 8, d = e & 255;
    float4 v = *(const float4*)&Q[base + (size_t)(q0 + row) * DIM + d];
    Qs[(d+0)*64+row]=v.x; Qs[(d+1)*64+row]=v.y; Qs[(d+2)*64+row]=v.z; Qs[(d+3)*64+row]=v.w;
  }
  if (tid < 64) { Ms[tid] = -INFINITY; Ls[tid] = 0.f; }
  float o[64];
#pragma unroll
  for (int i = 0; i < 64; i++) o[i] = 0.f;
  int i0 = (tid >> 4) << 2, j0 = (tid & 15) << 2;

  for (int kt = 0; kt <= (int)blockIdx.x; kt++) {
    __syncthreads();   // prev PV done before overwriting Ks/Vs/Ps
#pragma unroll
    for (int rep = 0; rep < 16; rep++) {
      int e = rep * 1024 + tid * 4;
      int row = e >> 8, d = e & 255;
      size_t g = base + (size_t)(kt * 64 + row) * DIM + d;
      float4 kv = *(const float4*)&Kb[g];
      Ks[(d+0)*64+row]=kv.x; Ks[(d+1)*64+row]=kv.y; Ks[(d+2)*64+row]=kv.z; Ks[(d+3)*64+row]=kv.w;
      float4 vv = *(const float4*)&V[g];
      *(float4*)&Vs[row * 256 + d] = vv;
    }
    __syncthreads();
    // S = Q K^T
    float acc[4][4] = {};
#pragma unroll 4
    for (int d = 0; d < 256; d++) {
      float4 av = *(const float4*)&Qs[d * 64 + i0];
      float4 bv = *(const float4*)&Ks[d * 64 + j0];
      FMA16(av, bv)
    }
#pragma unroll
    for (int ii = 0; ii < 4; ii++)
      *(float4*)&Ps[(i0 + ii) * 64 + j0] =
          make_float4(acc[ii][0], acc[ii][1], acc[ii][2], acc[ii][3]);
    __syncthreads();
    // online softmax, one thread per row
    if (tid < 64) {
      int i = tid;
      int jmax = min(64, q0 + i - kt * 64 + 1);   // causal: k-index <= q-index
      float mx = Ms[i];
      for (int j = 0; j < jmax; j++) mx = fmaxf(mx, Ps[i * 64 + j]);
      float scale = __expf(Ms[i] - mx);
      float sum = 0.f;
      for (int j = 0; j < 64; j++) {
        float p = (j < jmax) ? __expf(Ps[i * 64 + j] - mx) : 0.f;
        Ps[i * 64 + j] = p;
        sum += p;
      }
      Ls[i] = Ls[i] * scale + sum;
      Ms[i] = mx;
      Ss[i] = scale;
    }
    __syncthreads();
    // O = O*scale + P @ V ; thread owns column c = tid
    int c = tid;
#pragma unroll
    for (int i = 0; i < 64; i++) o[i] *= Ss[i];
    for (int j = 0; j < 64; j += 4) {
      float v0 = Vs[(j+0)*256+c], v1 = Vs[(j+1)*256+c];
      float v2 = Vs[(j+2)*256+c], v3 = Vs[(j+3)*256+c];
#pragma unroll
      for (int i = 0; i < 64; i++) {
        float4 p = *(const float4*)&Ps[i * 64 + j];
        o[i] += p.x*v0 + p.y*v1 + p.z*v2 + p.w*v3;
      }
    }
  }
  int c = tid;
#pragma unroll
  for (int i = 0; i < 64; i++)
    O[base + (size_t)(q0 + i) * DIM + c] = o[i] / Ls[i];
}

// ---------------------------------------------------------------------------
// denQ[r][h] = elu1(Q[r,h,:]) . z[h,:] ; denK analogous. grid 8192 x 256.
// ---------------------------------------------------------------------------
__global__ void __launch_bounds__(256) den_kernel(const float* __restrict__ Q,
    const float* __restrict__ Kb, const float* __restrict__ z,
    float* __restrict__ denQ, float* __restrict__ denK) {
  __shared__ float sq[256], sk[256];
  int r = blockIdx.x, tid = threadIdx.x;
  int h = tid >> 6, dd = (tid & 63) << 2;
  float4 zv = *(const float4*)&z[h * HDIM + dd];
  float4 qv = *(const float4*)&Q[(size_t)r * DIM + h * HDIM + dd];
  float4 kv = *(const float4*)&Kb[(size_t)r * DIM + h * HDIM + dd];
  sq[tid] = elu1(qv.x)*zv.x + elu1(qv.y)*zv.y + elu1(qv.z)*zv.z + elu1(qv.w)*zv.w;
  sk[tid] = elu1(kv.x)*zv.x + elu1(kv.y)*zv.y + elu1(kv.z)*zv.z + elu1(kv.w)*zv.w;
  __syncthreads();
  if (tid < 8) {
    int hh = tid & 3;
    const float* buf = (tid < 4) ? sq : sk;
    float s = 0.f;
    for (int t = 0; t < 64; t++) s += buf[hh * 64 + t];
    if (tid < 4) denQ[r * 4 + hh] = s; else denK[r * 4 + hh] = s;
  }
}

// U = V - NUMK / (denK + 1e-6)   (in place on V)
__global__ void __launch_bounds__(256) u_update(float* __restrict__ V,
    const float* __restrict__ NUM, const float* __restrict__ denK) {
  int idx = blockIdx.x * 256 + threadIdx.x;
  int e = idx << 2;
  int r = e >> 10, h = (e >> 8) & 3;
  float inv = 1.f / (denK[r * 4 + h] + 1e-6f);
  float4 n = *(const float4*)&NUM[e];
  float4 v = *(float4*)&V[e];
  v.x -= n.x * inv; v.y -= n.y * inv; v.z -= n.z * inv; v.w -= n.w * inv;
  *(float4*)&V[e] = v;
}

// NUM = g * NUM/(denQ+1e-6) + (1-g) * ATTN   (in place on NUM)
__global__ void __launch_bounds__(256) blend_kernel(float* __restrict__ NUM,
    const float* __restrict__ ATTN, const float* __restrict__ denQ,
    const float* __restrict__ betas) {
  int idx = blockIdx.x * 256 + threadIdx.x;
  int e = idx << 2;
  int r = e >> 10, h = (e >> 8) & 3;
  float g = 1.f / (1.f + __expf(-betas[h]));
  float inv = g / (denQ[r * 4 + h] + 1e-6f);
  float om = 1.f - g;
  float4 n = *(float4*)&NUM[e];
  float4 a = *(const float4*)&ATTN[e];
  n.x = n.x * inv + om * a.x;
  n.y = n.y * inv + om * a.y;
  n.z = n.z * inv + om * a.z;
  n.w = n.w * inv + om * a.w;
  *(float4*)&NUM[e] = n;
}

// z_new[col] = z[col] + 0.25 * sum_r elu1(K[r][col]).  grid 16, block 256.
__global__ void __launch_bounds__(256) zsum_kernel(const float* __restrict__ Kb,
    const float* __restrict__ z, float* __restrict__ outz) {
  __shared__ float red[256];
  int tid = threadIdx.x;
  int col = blockIdx.x * 64 + (tid & 63);
  int rl = tid >> 6;
  float s = 0.f;
  for (int r = rl; r < R_ROWS; r += 4) s += elu1(Kb[(size_t)r * DIM + col]);
  red[tid] = s;
  __syncthreads();
  if (tid < 64) {
    int c = blockIdx.x * 64 + tid;
    outz[c] = z[c] + 0.25f * (red[tid] + red[tid + 64] + red[tid + 128] + red[tid + 192]);
  }
}

// ---------------------------------------------------------------------------
extern "C" void kernel_launch(void* const* d_in, const int* in_sizes, int n_in,
                              void* d_out, int out_size) {
  const float* X     = (const float*)d_in[0];
  const float* Wq    = (const float*)d_in[1];
  const float* Wk    = (const float*)d_in[2];
  const float* Wv    = (const float*)d_in[3];
  const float* Wo    = (const float*)d_in[4];
  const float* bo    = (const float*)d_in[5];
  const float* betas = (const float*)d_in[6];
  const float* memin = (const float*)d_in[7];
  const float* zin   = (const float*)d_in[8];
  float* out     = (float*)d_out;
  float* out_mem = out + 8388608;   // [4,256,256]
  float* out_z   = out + 8650752;   // [4,256,1]

  float *pQ, *pK, *pV, *pA, *pN, *pDQ, *pDK;
  cudaGetSymbolAddress((void**)&pQ,  g_Q);
  cudaGetSymbolAddress((void**)&pK,  g_K);
  cudaGetSymbolAddress((void**)&pV,  g_V);
  cudaGetSymbolAddress((void**)&pA,  g_ATTN);
  cudaGetSymbolAddress((void**)&pN,  g_NUM);
  cudaGetSymbolAddress((void**)&pDQ, g_DENQ);
  cudaGetSymbolAddress((void**)&pDK, g_DENK);

  dim3 gproj(16, 128);
  // Projections
  gemm_tn<<<gproj, 256>>>(X, Wq, nullptr, pQ, R_ROWS, DIM, DIM);
  gemm_tn<<<gproj, 256>>>(X, Wk, nullptr, pK, R_ROWS, DIM, DIM);
  gemm_tn<<<gproj, 256>>>(X, Wv, nullptr, pV, R_ROWS, DIM, DIM);

  // Causal attention
  cudaFuncSetAttribute(flash_kernel, cudaFuncAttributeMaxDynamicSharedMemorySize, FL_SMEM);
  flash_kernel<<<dim3(32, 16), 256, FL_SMEM>>>(pQ, pK, pV, pA);

  // delta-rule path: NUMK = elu1(K)@mem ; denK ; U = V - NUMK/(denK+eps)
  gemm_nn_elu<<<dim3(4, 128, 4), 256>>>(pK, memin, pN);
  den_kernel<<<R_ROWS, 256>>>(pQ, pK, zin, pDQ, pDK);
  u_update<<<R_ROWS, 256>>>(pV, pN, pDK);

  // state updates -> d_out tail
  gemm_atb<<<dim3(4, 4, 4), 256>>>(pK, pV, memin, out_mem);
  zsum_kernel<<<16, 256>>>(pK, zin, out_z);

  // memory read path: NUMQ = elu1(Q)@mem ; blend with attention
  gemm_nn_elu<<<dim3(4, 128, 4), 256>>>(pQ, memin, pN);
  blend_kernel<<<R_ROWS, 256>>>(pN, pA, pDQ, betas);

  // output projection (+bias) -> d_out head
  gemm_tn<<<gproj, 256>>>(pN, Wo, bo, out, R_ROWS, DIM, DIM);
}

// round 6
// speedup vs baseline: 1.1516x; 1.1516x over previous
#include <cuda_runtime.h>
#include <cuda_bf16.h>
#include <mma.h>
#include <math.h>

using namespace nvcuda;

// Problem constants: B=4, S=2048, D=1024, H=4, HD=256, R=B*S=8192
#define R_ROWS 8192
#define DIM    1024
#define NHEAD  4
#define HDIM   256

// Scratch (no allocation allowed -> device globals)
__device__ float g_Q[8388608];
__device__ float g_K[8388608];
__device__ float g_V[8388608];
__device__ float g_ATTN[8388608];
__device__ float g_NUM[8388608];
__device__ float g_DENQ[32768];
__device__ float g_DENK[32768];

__device__ __forceinline__ float elu1(float x) { return x > 0.f ? x + 1.f : __expf(x); }

// fp32 -> (hi, lo) bf16 split stored to two smem arrays
__device__ __forceinline__ void cvt_split(float x, __nv_bfloat16* dh,
                                          __nv_bfloat16* dl, int off) {
  __nv_bfloat16 h = __float2bfloat16(x);
  dh[off] = h;
  dl[off] = __float2bfloat16(x - __bfloat162float(h));
}
__device__ __forceinline__ void stage4(float4 a, __nv_bfloat16* h,
                                       __nv_bfloat16* l, int off) {
  cvt_split(a.x, h, l, off);
  cvt_split(a.y, h, l, off + 1);
  cvt_split(a.z, h, l, off + 2);
  cvt_split(a.w, h, l, off + 3);
}
// 4x4 outer-product FMA into acc
__device__ __forceinline__ void fma16(float acc[4][4], const float4 av, const float4 bv) {
  acc[0][0]+=av.x*bv.x; acc[0][1]+=av.x*bv.y; acc[0][2]+=av.x*bv.z; acc[0][3]+=av.x*bv.w;
  acc[1][0]+=av.y*bv.x; acc[1][1]+=av.y*bv.y; acc[1][2]+=av.y*bv.z; acc[1][3]+=av.y*bv.w;
  acc[2][0]+=av.z*bv.x; acc[2][1]+=av.z*bv.y; acc[2][2]+=av.z*bv.z; acc[2][3]+=av.z*bv.w;
  acc[3][0]+=av.w*bv.x; acc[3][1]+=av.w*bv.y; acc[3][2]+=av.w*bv.z; acc[3][3]+=av.w*bv.w;
}

// ---------------------------------------------------------------------------
// C[M,N] = A[M,K] @ B[N,K]^T (+bias), WMMA bf16 3-pass split (hi/lo).
// CTA tile 128x64, BK=16, 8 warps (4m x 2n), warp tile 32x32.
// ---------------------------------------------------------------------------
__global__ void __launch_bounds__(256) gemm_tn_wmma(const float* __restrict__ A,
    const float* __restrict__ Bw, const float* __restrict__ bias,
    float* __restrict__ C, int M, int N, int K) {
  __shared__ char smraw[40960];
  __nv_bfloat16* sAh = (__nv_bfloat16*)smraw;   // [128][24]
  __nv_bfloat16* sAl = sAh + 3072;
  __nv_bfloat16* sBh = sAl + 3072;              // [64][24]
  __nv_bfloat16* sBl = sBh + 1536;

  int t = threadIdx.x, lane = t & 31, warp = t >> 5;
  int wm = warp & 3, wn = warp >> 2;
  int m0 = blockIdx.y * 128, n0 = blockIdx.x * 64;

  // A stage: thread covers row = t>>1 (0..127), 8 floats at col (t&1)*8
  int arow = t >> 1, acol = (t & 1) << 3;
  // B stage: thread covers row = t>>2 (0..63), 4 floats at col (t&3)*4
  int brow = t >> 2, bcol = (t & 3) << 2;
  const float* Ap = A + (size_t)(m0 + arow) * K + acol;
  const float* Bp = Bw + (size_t)(n0 + brow) * K + bcol;
  int sa = arow * 24 + acol;
  int sb = brow * 24 + bcol;

  wmma::fragment<wmma::accumulator, 16, 16, 16, float> acc[2][2];
#pragma unroll
  for (int mi = 0; mi < 2; mi++)
#pragma unroll
    for (int ni = 0; ni < 2; ni++) wmma::fill_fragment(acc[mi][ni], 0.f);

  float4 ra0, ra1, rbv;
  ra0 = *(const float4*)(Ap);
  ra1 = *(const float4*)(Ap + 4);
  rbv = *(const float4*)(Bp);
  stage4(ra0, sAh, sAl, sa);
  stage4(ra1, sAh, sAl, sa + 4);
  stage4(rbv, sBh, sBl, sb);
  __syncthreads();

  int nk = K >> 4;
  for (int kt = 0; kt < nk; kt++) {
    bool more = (kt + 1 < nk);
    if (more) {
      int k0 = (kt + 1) << 4;
      ra0 = *(const float4*)(Ap + k0);
      ra1 = *(const float4*)(Ap + k0 + 4);
      rbv = *(const float4*)(Bp + k0);
    }

    wmma::fragment<wmma::matrix_a, 16, 16, 16, __nv_bfloat16, wmma::row_major> fah[2], fal[2];
    wmma::fragment<wmma::matrix_b, 16, 16, 16, __nv_bfloat16, wmma::col_major> fbh[2], fbl[2];
#pragma unroll
    for (int mi = 0; mi < 2; mi++) {
      wmma::load_matrix_sync(fah[mi], sAh + (wm * 32 + mi * 16) * 24, 24);
      wmma::load_matrix_sync(fal[mi], sAl + (wm * 32 + mi * 16) * 24, 24);
    }
#pragma unroll
    for (int ni = 0; ni < 2; ni++) {
      wmma::load_matrix_sync(fbh[ni], sBh + (wn * 32 + ni * 16) * 24, 24);
      wmma::load_matrix_sync(fbl[ni], sBl + (wn * 32 + ni * 16) * 24, 24);
    }
#pragma unroll
    for (int mi = 0; mi < 2; mi++)
#pragma unroll
      for (int ni = 0; ni < 2; ni++) {
        wmma::mma_sync(acc[mi][ni], fah[mi], fbh[ni], acc[mi][ni]);
        wmma::mma_sync(acc[mi][ni], fah[mi], fbl[ni], acc[mi][ni]);
        wmma::mma_sync(acc[mi][ni], fal[mi], fbh[ni], acc[mi][ni]);
      }
    __syncthreads();
    if (more) {
      stage4(ra0, sAh, sAl, sa);
      stage4(ra1, sAh, sAl, sa + 4);
      stage4(rbv, sBh, sBl, sb);
      __syncthreads();
    }
  }

  // epilogue: stage acc to smem (per-warp [32][40] fp32), add bias, store
  float* ep = (float*)smraw + warp * 1280;
#pragma unroll
  for (int mi = 0; mi < 2; mi++)
#pragma unroll
    for (int ni = 0; ni < 2; ni++)
      wmma::store_matrix_sync(ep + mi * 16 * 40 + ni * 16, acc[mi][ni], 40,
                              wmma::mem_row_major);
  __syncwarp();
  int m = m0 + wm * 32 + lane;
  int nc0 = n0 + wn * 32;
#pragma unroll
  for (int c = 0; c < 32; c += 4) {
    float4 v = *(float4*)&ep[lane * 40 + c];
    if (bias) {
      float4 bb = *(const float4*)&bias[nc0 + c];
      v.x += bb.x; v.y += bb.y; v.z += bb.z; v.w += bb.w;
    }
    *(float4*)&C[(size_t)m * N + nc0 + c] = v;
  }
}

// ---------------------------------------------------------------------------
// NUM[r][h*256+n] = sum_d elu1(X[r][h*256+d]) * Mem[h][d][n]   (K=256)
// ---------------------------------------------------------------------------
__global__ void __launch_bounds__(256) gemm_nn_elu(const float* __restrict__ X,
    const float* __restrict__ Mem, float* __restrict__ C) {
  __shared__ float As[16][64];
  __shared__ float Bs[16][64];
  int tid = threadIdx.x;
  int h = blockIdx.z;
  int m0 = blockIdx.y * 64, n0 = blockIdx.x * 64;
  int i0 = (tid >> 4) << 2, j0 = (tid & 15) << 2;
  int lr = tid >> 2, lk = (tid & 3) << 2;
  int br = tid >> 4, bc = (tid & 15) << 2;
  const float* Mh = Mem + (size_t)h * 65536;
  float acc[4][4] = {};
  for (int k0 = 0; k0 < 256; k0 += 16) {
    float4 a = *(const float4*)&X[(size_t)(m0 + lr) * DIM + h * HDIM + k0 + lk];
    float4 b = *(const float4*)&Mh[(size_t)(k0 + br) * HDIM + n0 + bc];
    __syncthreads();
    As[lk+0][lr]=elu1(a.x); As[lk+1][lr]=elu1(a.y); As[lk+2][lr]=elu1(a.z); As[lk+3][lr]=elu1(a.w);
    *(float4*)&Bs[br][bc] = b;
    __syncthreads();
#pragma unroll
    for (int kk = 0; kk < 16; kk++) {
      float4 av = *(const float4*)&As[kk][i0];
      float4 bv = *(const float4*)&Bs[kk][j0];
      fma16(acc, av, bv);
    }
  }
#pragma unroll
  for (int ii = 0; ii < 4; ii++) {
    float4 r = make_float4(acc[ii][0], acc[ii][1], acc[ii][2], acc[ii][3]);
    *(float4*)&C[(size_t)(m0 + i0 + ii) * DIM + h * HDIM + n0 + j0] = r;
  }
}

// ---------------------------------------------------------------------------
// mem_new[h][d][e] = mem[h][d][e] + 0.25 * sum_r elu1(K[r][h*256+d]) * U[r][h*256+e]
// ---------------------------------------------------------------------------
__global__ void __launch_bounds__(256) gemm_atb(const float* __restrict__ Kb,
    const float* __restrict__ U, const float* __restrict__ Memin,
    float* __restrict__ Out) {
  __shared__ float As[16][64];
  __shared__ float Bs[16][64];
  int tid = threadIdx.x;
  int h = blockIdx.z;
  int d0 = blockIdx.y * 64, e0 = blockIdx.x * 64;
  int i0 = (tid >> 4) << 2, j0 = (tid & 15) << 2;
  int br = tid >> 4, bc = (tid & 15) << 2;
  float acc[4][4] = {};
  for (int r0 = 0; r0 < R_ROWS; r0 += 16) {
    float4 a = *(const float4*)&Kb[(size_t)(r0 + br) * DIM + h * HDIM + d0 + bc];
    float4 b = *(const float4*)&U[(size_t)(r0 + br) * DIM + h * HDIM + e0 + bc];
    __syncthreads();
    As[br][bc+0]=elu1(a.x); As[br][bc+1]=elu1(a.y); As[br][bc+2]=elu1(a.z); As[br][bc+3]=elu1(a.w);
    *(float4*)&Bs[br][bc] = b;
    __syncthreads();
#pragma unroll
    for (int kk = 0; kk < 16; kk++) {
      float4 av = *(const float4*)&As[kk][i0];
      float4 bv = *(const float4*)&Bs[kk][j0];
      fma16(acc, av, bv);
    }
  }
#pragma unroll
  for (int ii = 0; ii < 4; ii++) {
    size_t idx = (size_t)h * 65536 + (size_t)(d0 + i0 + ii) * HDIM + e0 + j0;
    float4 m = *(const float4*)&Memin[idx];
    float4 r = make_float4(m.x + 0.25f*acc[ii][0], m.y + 0.25f*acc[ii][1],
                           m.z + 0.25f*acc[ii][2], m.w + 0.25f*acc[ii][3]);
    *(float4*)&Out[idx] = r;
  }
}

// ---------------------------------------------------------------------------
// Flash attention (causal, no scaling). grid(32 q-tiles, 16 b*h), 256 threads.
// ---------------------------------------------------------------------------
#define FL_SMEM ((16384*3 + 4096 + 192) * 4)

__global__ void __launch_bounds__(256) flash_kernel(const float* __restrict__ Q,
    const float* __restrict__ Kb, const float* __restrict__ V,
    float* __restrict__ O) {
  extern __shared__ float sm[];
  float* Qs = sm;            // [256][64]
  float* Ks = sm + 16384;    // [256][64]
  float* Vs = sm + 32768;    // [64][256]
  float* Ps = sm + 49152;    // [64][64]
  float* Ms = sm + 53248;    // [64]
  float* Ls = sm + 53312;    // [64]
  float* Ss = sm + 53376;    // [64]
  int tid = threadIdx.x;
  int b = blockIdx.y >> 2, h = blockIdx.y & 3;
  size_t base = (size_t)b * (2048 * 1024) + h * HDIM;
  int q0 = blockIdx.x * 64;

#pragma unroll
  for (int rep = 0; rep < 16; rep++) {
    int e = rep * 1024 + tid * 4;
    int row = e >> 8, d = e & 255;
    float4 v = *(const float4*)&Q[base + (size_t)(q0 + row) * DIM + d];
    Qs[(d+0)*64+row]=v.x; Qs[(d+1)*64+row]=v.y; Qs[(d+2)*64+row]=v.z; Qs[(d+3)*64+row]=v.w;
  }
  if (tid < 64) { Ms[tid] = -INFINITY; Ls[tid] = 0.f; }
  float o[64];
#pragma unroll
  for (int i = 0; i < 64; i++) o[i] = 0.f;
  int i0 = (tid >> 4) << 2, j0 = (tid & 15) << 2;

  for (int kt = 0; kt <= (int)blockIdx.x; kt++) {
    __syncthreads();
#pragma unroll
    for (int rep = 0; rep < 16; rep++) {
      int e = rep * 1024 + tid * 4;
      int row = e >> 8, d = e & 255;
      size_t g = base + (size_t)(kt * 64 + row) * DIM + d;
      float4 kv = *(const float4*)&Kb[g];
      Ks[(d+0)*64+row]=kv.x; Ks[(d+1)*64+row]=kv.y; Ks[(d+2)*64+row]=kv.z; Ks[(d+3)*64+row]=kv.w;
      float4 vv = *(const float4*)&V[g];
      *(float4*)&Vs[row * 256 + d] = vv;
    }
    __syncthreads();
    float acc[4][4] = {};
#pragma unroll 4
    for (int d = 0; d < 256; d++) {
      float4 av = *(const float4*)&Qs[d * 64 + i0];
      float4 bv = *(const float4*)&Ks[d * 64 + j0];
      fma16(acc, av, bv);
    }
#pragma unroll
    for (int ii = 0; ii < 4; ii++)
      *(float4*)&Ps[(i0 + ii) * 64 + j0] =
          make_float4(acc[ii][0], acc[ii][1], acc[ii][2], acc[ii][3]);
    __syncthreads();
    if (tid < 64) {
      int i = tid;
      int jmax = min(64, q0 + i - kt * 64 + 1);
      float mx = Ms[i];
      for (int j = 0; j < jmax; j++) mx = fmaxf(mx, Ps[i * 64 + j]);
      float scale = __expf(Ms[i] - mx);
      float sum = 0.f;
      for (int j = 0; j < 64; j++) {
        float p = (j < jmax) ? __expf(Ps[i * 64 + j] - mx) : 0.f;
        Ps[i * 64 + j] = p;
        sum += p;
      }
      Ls[i] = Ls[i] * scale + sum;
      Ms[i] = mx;
      Ss[i] = scale;
    }
    __syncthreads();
    int c = tid;
#pragma unroll
    for (int i = 0; i < 64; i++) o[i] *= Ss[i];
    for (int j = 0; j < 64; j += 4) {
      float v0 = Vs[(j+0)*256+c], v1 = Vs[(j+1)*256+c];
      float v2 = Vs[(j+2)*256+c], v3 = Vs[(j+3)*256+c];
#pragma unroll
      for (int i = 0; i < 64; i++) {
        float4 p = *(const float4*)&Ps[i * 64 + j];
        o[i] += p.x*v0 + p.y*v1 + p.z*v2 + p.w*v3;
      }
    }
  }
  int c = tid;
#pragma unroll
  for (int i = 0; i < 64; i++)
    O[base + (size_t)(q0 + i) * DIM + c] = o[i] / Ls[i];
}

// ---------------------------------------------------------------------------
__global__ void __launch_bounds__(256) den_kernel(const float* __restrict__ Q,
    const float* __restrict__ Kb, const float* __restrict__ z,
    float* __restrict__ denQ, float* __restrict__ denK) {
  __shared__ float sq[256], sk[256];
  int r = blockIdx.x, tid = threadIdx.x;
  int h = tid >> 6, dd = (tid & 63) << 2;
  float4 zv = *(const float4*)&z[h * HDIM + dd];
  float4 qv = *(const float4*)&Q[(size_t)r * DIM + h * HDIM + dd];
  float4 kv = *(const float4*)&Kb[(size_t)r * DIM + h * HDIM + dd];
  sq[tid] = elu1(qv.x)*zv.x + elu1(qv.y)*zv.y + elu1(qv.z)*zv.z + elu1(qv.w)*zv.w;
  sk[tid] = elu1(kv.x)*zv.x + elu1(kv.y)*zv.y + elu1(kv.z)*zv.z + elu1(kv.w)*zv.w;
  __syncthreads();
  if (tid < 8) {
    int hh = tid & 3;
    const float* buf = (tid < 4) ? sq : sk;
    float s = 0.f;
    for (int t = 0; t < 64; t++) s += buf[hh * 64 + t];
    if (tid < 4) denQ[r * 4 + hh] = s; else denK[r * 4 + hh] = s;
  }
}

__global__ void __launch_bounds__(256) u_update(float* __restrict__ V,
    const float* __restrict__ NUM, const float* __restrict__ denK) {
  int idx = blockIdx.x * 256 + threadIdx.x;
  int e = idx << 2;
  int r = e >> 10, h = (e >> 8) & 3;
  float inv = 1.f / (denK[r * 4 + h] + 1e-6f);
  float4 n = *(const float4*)&NUM[e];
  float4 v = *(float4*)&V[e];
  v.x -= n.x * inv; v.y -= n.y * inv; v.z -= n.z * inv; v.w -= n.w * inv;
  *(float4*)&V[e] = v;
}

__global__ void __launch_bounds__(256) blend_kernel(float* __restrict__ NUM,
    const float* __restrict__ ATTN, const float* __restrict__ denQ,
    const float* __restrict__ betas) {
  int idx = blockIdx.x * 256 + threadIdx.x;
  int e = idx << 2;
  int r = e >> 10, h = (e >> 8) & 3;
  float g = 1.f / (1.f + __expf(-betas[h]));
  float inv = g / (denQ[r * 4 + h] + 1e-6f);
  float om = 1.f - g;
  float4 n = *(float4*)&NUM[e];
  float4 a = *(const float4*)&ATTN[e];
  n.x = n.x * inv + om * a.x;
  n.y = n.y * inv + om * a.y;
  n.z = n.z * inv + om * a.z;
  n.w = n.w * inv + om * a.w;
  *(float4*)&NUM[e] = n;
}

__global__ void __launch_bounds__(256) zsum_kernel(const float* __restrict__ Kb,
    const float* __restrict__ z, float* __restrict__ outz) {
  __shared__ float red[256];
  int tid = threadIdx.x;
  int col = blockIdx.x * 64 + (tid & 63);
  int rl = tid >> 6;
  float s = 0.f;
  for (int r = rl; r < R_ROWS; r += 4) s += elu1(Kb[(size_t)r * DIM + col]);
  red[tid] = s;
  __syncthreads();
  if (tid < 64) {
    int c = blockIdx.x * 64 + tid;
    outz[c] = z[c] + 0.25f * (red[tid] + red[tid + 64] + red[tid + 128] + red[tid + 192]);
  }
}

// ---------------------------------------------------------------------------
extern "C" void kernel_launch(void* const* d_in, const int* in_sizes, int n_in,
                              void* d_out, int out_size) {
  const float* X     = (const float*)d_in[0];
  const float* Wq    = (const float*)d_in[1];
  const float* Wk    = (const float*)d_in[2];
  const float* Wv    = (const float*)d_in[3];
  const float* Wo    = (const float*)d_in[4];
  const float* bo    = (const float*)d_in[5];
  const float* betas = (const float*)d_in[6];
  const float* memin = (const float*)d_in[7];
  const float* zin   = (const float*)d_in[8];
  float* out     = (float*)d_out;
  float* out_mem = out + 8388608;   // [4,256,256]
  float* out_z   = out + 8650752;   // [4,256,1]

  float *pQ, *pK, *pV, *pA, *pN, *pDQ, *pDK;
  cudaGetSymbolAddress((void**)&pQ,  g_Q);
  cudaGetSymbolAddress((void**)&pK,  g_K);
  cudaGetSymbolAddress((void**)&pV,  g_V);
  cudaGetSymbolAddress((void**)&pA,  g_ATTN);
  cudaGetSymbolAddress((void**)&pN,  g_NUM);
  cudaGetSymbolAddress((void**)&pDQ, g_DENQ);
  cudaGetSymbolAddress((void**)&pDK, g_DENK);

  dim3 gmma(DIM / 64, R_ROWS / 128);  // (16, 64)
  // Projections (WMMA tensor cores, bf16 3-pass)
  gemm_tn_wmma<<<gmma, 256>>>(X, Wq, nullptr, pQ, R_ROWS, DIM, DIM);
  gemm_tn_wmma<<<gmma, 256>>>(X, Wk, nullptr, pK, R_ROWS, DIM, DIM);
  gemm_tn_wmma<<<gmma, 256>>>(X, Wv, nullptr, pV, R_ROWS, DIM, DIM);

  // Causal attention
  cudaFuncSetAttribute(flash_kernel, cudaFuncAttributeMaxDynamicSharedMemorySize, FL_SMEM);
  flash_kernel<<<dim3(32, 16), 256, FL_SMEM>>>(pQ, pK, pV, pA);

  // delta-rule path
  gemm_nn_elu<<<dim3(4, 128, 4), 256>>>(pK, memin, pN);
  den_kernel<<<R_ROWS, 256>>>(pQ, pK, zin, pDQ, pDK);
  u_update<<<R_ROWS, 256>>>(pV, pN, pDK);

  // state updates
  gemm_atb<<<dim3(4, 4, 4), 256>>>(pK, pV, memin, out_mem);
  zsum_kernel<<<16, 256>>>(pK, zin, out_z);

  // memory read path + blend
  gemm_nn_elu<<<dim3(4, 128, 4), 256>>>(pQ, memin, pN);
  blend_kernel<<<R_ROWS, 256>>>(pN, pA, pDQ, betas);

  // output projection (+bias)
  gemm_tn_wmma<<<gmma, 256>>>(pN, Wo, bo, out, R_ROWS, DIM, DIM);
}

// round 7
// speedup vs baseline: 1.5157x; 1.3162x over previous
#include <cuda_runtime.h>
#include <cuda_bf16.h>
#include <mma.h>
#include <math.h>

using namespace nvcuda;

// Problem constants: B=4, S=2048, D=1024, H=4, HD=256, R=B*S=8192
#define R_ROWS 8192
#define DIM    1024
#define NHEAD  4
#define HDIM   256

// Scratch (no allocation allowed -> device globals)
__device__ float g_Q[8388608];
__device__ float g_K[8388608];
__device__ float g_V[8388608];
__device__ float g_ATTN[8388608];
__device__ float g_NUM[8388608];
__device__ float g_DENQ[32768];
__device__ float g_DENK[32768];

__device__ __forceinline__ float elu1(float x) { return x > 0.f ? x + 1.f : __expf(x); }

// fp32 -> (hi, lo) bf16 split stored to two smem arrays
__device__ __forceinline__ void cvt_split(float x, __nv_bfloat16* dh,
                                          __nv_bfloat16* dl, int off) {
  __nv_bfloat16 h = __float2bfloat16(x);
  dh[off] = h;
  dl[off] = __float2bfloat16(x - __bfloat162float(h));
}
__device__ __forceinline__ void stage4(float4 a, __nv_bfloat16* h,
                                       __nv_bfloat16* l, int off) {
  cvt_split(a.x, h, l, off);
  cvt_split(a.y, h, l, off + 1);
  cvt_split(a.z, h, l, off + 2);
  cvt_split(a.w, h, l, off + 3);
}
// 4x4 outer-product FMA into acc
__device__ __forceinline__ void fma16(float acc[4][4], const float4 av, const float4 bv) {
  acc[0][0]+=av.x*bv.x; acc[0][1]+=av.x*bv.y; acc[0][2]+=av.x*bv.z; acc[0][3]+=av.x*bv.w;
  acc[1][0]+=av.y*bv.x; acc[1][1]+=av.y*bv.y; acc[1][2]+=av.y*bv.z; acc[1][3]+=av.y*bv.w;
  acc[2][0]+=av.z*bv.x; acc[2][1]+=av.z*bv.y; acc[2][2]+=av.z*bv.z; acc[2][3]+=av.z*bv.w;
  acc[3][0]+=av.w*bv.x; acc[3][1]+=av.w*bv.y; acc[3][2]+=av.w*bv.z; acc[3][3]+=av.w*bv.w;
}

// ---------------------------------------------------------------------------
// C[M,N] = A[M,K] @ B[N,K]^T (+bias), WMMA bf16 3-pass split (hi/lo).
// CTA tile 128x64, BK=16, 8 warps (4m x 2n), warp tile 32x32.
// ---------------------------------------------------------------------------
__global__ void __launch_bounds__(256) gemm_tn_wmma(const float* __restrict__ A,
    const float* __restrict__ Bw, const float* __restrict__ bias,
    float* __restrict__ C, int M, int N, int K) {
  __shared__ char smraw[40960];
  __nv_bfloat16* sAh = (__nv_bfloat16*)smraw;   // [128][24]
  __nv_bfloat16* sAl = sAh + 3072;
  __nv_bfloat16* sBh = sAl + 3072;              // [64][24]
  __nv_bfloat16* sBl = sBh + 1536;

  int t = threadIdx.x, lane = t & 31, warp = t >> 5;
  int wm = warp & 3, wn = warp >> 2;
  int m0 = blockIdx.y * 128, n0 = blockIdx.x * 64;

  int arow = t >> 1, acol = (t & 1) << 3;
  int brow = t >> 2, bcol = (t & 3) << 2;
  const float* Ap = A + (size_t)(m0 + arow) * K + acol;
  const float* Bp = Bw + (size_t)(n0 + brow) * K + bcol;
  int sa = arow * 24 + acol;
  int sb = brow * 24 + bcol;

  wmma::fragment<wmma::accumulator, 16, 16, 16, float> acc[2][2];
#pragma unroll
  for (int mi = 0; mi < 2; mi++)
#pragma unroll
    for (int ni = 0; ni < 2; ni++) wmma::fill_fragment(acc[mi][ni], 0.f);

  float4 ra0, ra1, rbv;
  ra0 = *(const float4*)(Ap);
  ra1 = *(const float4*)(Ap + 4);
  rbv = *(const float4*)(Bp);
  stage4(ra0, sAh, sAl, sa);
  stage4(ra1, sAh, sAl, sa + 4);
  stage4(rbv, sBh, sBl, sb);
  __syncthreads();

  int nk = K >> 4;
  for (int kt = 0; kt < nk; kt++) {
    bool more = (kt + 1 < nk);
    if (more) {
      int k0 = (kt + 1) << 4;
      ra0 = *(const float4*)(Ap + k0);
      ra1 = *(const float4*)(Ap + k0 + 4);
      rbv = *(const float4*)(Bp + k0);
    }

    wmma::fragment<wmma::matrix_a, 16, 16, 16, __nv_bfloat16, wmma::row_major> fah[2], fal[2];
    wmma::fragment<wmma::matrix_b, 16, 16, 16, __nv_bfloat16, wmma::col_major> fbh[2], fbl[2];
#pragma unroll
    for (int mi = 0; mi < 2; mi++) {
      wmma::load_matrix_sync(fah[mi], sAh + (wm * 32 + mi * 16) * 24, 24);
      wmma::load_matrix_sync(fal[mi], sAl + (wm * 32 + mi * 16) * 24, 24);
    }
#pragma unroll
    for (int ni = 0; ni < 2; ni++) {
      wmma::load_matrix_sync(fbh[ni], sBh + (wn * 32 + ni * 16) * 24, 24);
      wmma::load_matrix_sync(fbl[ni], sBl + (wn * 32 + ni * 16) * 24, 24);
    }
#pragma unroll
    for (int mi = 0; mi < 2; mi++)
#pragma unroll
      for (int ni = 0; ni < 2; ni++) {
        wmma::mma_sync(acc[mi][ni], fah[mi], fbh[ni], acc[mi][ni]);
        wmma::mma_sync(acc[mi][ni], fah[mi], fbl[ni], acc[mi][ni]);
        wmma::mma_sync(acc[mi][ni], fal[mi], fbh[ni], acc[mi][ni]);
      }
    __syncthreads();
    if (more) {
      stage4(ra0, sAh, sAl, sa);
      stage4(ra1, sAh, sAl, sa + 4);
      stage4(rbv, sBh, sBl, sb);
      __syncthreads();
    }
  }

  float* ep = (float*)smraw + warp * 1280;
#pragma unroll
  for (int mi = 0; mi < 2; mi++)
#pragma unroll
    for (int ni = 0; ni < 2; ni++)
      wmma::store_matrix_sync(ep + mi * 16 * 40 + ni * 16, acc[mi][ni], 40,
                              wmma::mem_row_major);
  __syncwarp();
  int m = m0 + wm * 32 + lane;
  int nc0 = n0 + wn * 32;
#pragma unroll
  for (int c = 0; c < 32; c += 4) {
    float4 v = *(float4*)&ep[lane * 40 + c];
    if (bias) {
      float4 bb = *(const float4*)&bias[nc0 + c];
      v.x += bb.x; v.y += bb.y; v.z += bb.z; v.w += bb.w;
    }
    *(float4*)&C[(size_t)m * N + nc0 + c] = v;
  }
}

// ---------------------------------------------------------------------------
// NUM[r][h*256+n] = sum_d elu1(X[r][h*256+d]) * Mem[h][d][n]   (K=256)
// ---------------------------------------------------------------------------
__global__ void __launch_bounds__(256) gemm_nn_elu(const float* __restrict__ X,
    const float* __restrict__ Mem, float* __restrict__ C) {
  __shared__ float As[16][64];
  __shared__ float Bs[16][64];
  int tid = threadIdx.x;
  int h = blockIdx.z;
  int m0 = blockIdx.y * 64, n0 = blockIdx.x * 64;
  int i0 = (tid >> 4) << 2, j0 = (tid & 15) << 2;
  int lr = tid >> 2, lk = (tid & 3) << 2;
  int br = tid >> 4, bc = (tid & 15) << 2;
  const float* Mh = Mem + (size_t)h * 65536;
  float acc[4][4] = {};
  for (int k0 = 0; k0 < 256; k0 += 16) {
    float4 a = *(const float4*)&X[(size_t)(m0 + lr) * DIM + h * HDIM + k0 + lk];
    float4 b = *(const float4*)&Mh[(size_t)(k0 + br) * HDIM + n0 + bc];
    __syncthreads();
    As[lk+0][lr]=elu1(a.x); As[lk+1][lr]=elu1(a.y); As[lk+2][lr]=elu1(a.z); As[lk+3][lr]=elu1(a.w);
    *(float4*)&Bs[br][bc] = b;
    __syncthreads();
#pragma unroll
    for (int kk = 0; kk < 16; kk++) {
      float4 av = *(const float4*)&As[kk][i0];
      float4 bv = *(const float4*)&Bs[kk][j0];
      fma16(acc, av, bv);
    }
  }
#pragma unroll
  for (int ii = 0; ii < 4; ii++) {
    float4 r = make_float4(acc[ii][0], acc[ii][1], acc[ii][2], acc[ii][3]);
    *(float4*)&C[(size_t)(m0 + i0 + ii) * DIM + h * HDIM + n0 + j0] = r;
  }
}

// ---------------------------------------------------------------------------
// mem_new[h][d][e] = mem[h][d][e] + 0.25 * sum_r elu1(K[r][h*256+d]) * U[r][h*256+e]
// ---------------------------------------------------------------------------
__global__ void __launch_bounds__(256) gemm_atb(const float* __restrict__ Kb,
    const float* __restrict__ U, const float* __restrict__ Memin,
    float* __restrict__ Out) {
  __shared__ float As[16][64];
  __shared__ float Bs[16][64];
  int tid = threadIdx.x;
  int h = blockIdx.z;
  int d0 = blockIdx.y * 64, e0 = blockIdx.x * 64;
  int i0 = (tid >> 4) << 2, j0 = (tid & 15) << 2;
  int br = tid >> 4, bc = (tid & 15) << 2;
  float acc[4][4] = {};
  for (int r0 = 0; r0 < R_ROWS; r0 += 16) {
    float4 a = *(const float4*)&Kb[(size_t)(r0 + br) * DIM + h * HDIM + d0 + bc];
    float4 b = *(const float4*)&U[(size_t)(r0 + br) * DIM + h * HDIM + e0 + bc];
    __syncthreads();
    As[br][bc+0]=elu1(a.x); As[br][bc+1]=elu1(a.y); As[br][bc+2]=elu1(a.z); As[br][bc+3]=elu1(a.w);
    *(float4*)&Bs[br][bc] = b;
    __syncthreads();
#pragma unroll
    for (int kk = 0; kk < 16; kk++) {
      float4 av = *(const float4*)&As[kk][i0];
      float4 bv = *(const float4*)&Bs[kk][j0];
      fma16(acc, av, bv);
    }
  }
#pragma unroll
  for (int ii = 0; ii < 4; ii++) {
    size_t idx = (size_t)h * 65536 + (size_t)(d0 + i0 + ii) * HDIM + e0 + j0;
    float4 m = *(const float4*)&Memin[idx];
    float4 r = make_float4(m.x + 0.25f*acc[ii][0], m.y + 0.25f*acc[ii][1],
                           m.z + 0.25f*acc[ii][2], m.w + 0.25f*acc[ii][3]);
    *(float4*)&Out[idx] = r;
  }
}

// ---------------------------------------------------------------------------
// Flash attention, WMMA bf16 3-pass. grid(32 q-tiles, 16 b*h), 256 threads.
// smem: Qh/Ql [64][264], KVh/KVl [64][264] (K then V reuse), Sbuf fp32 [64][72],
//       Ph/Pl [64][72], stats. Total 172800 bytes.
// ---------------------------------------------------------------------------
#define FLW_SMEM 172800

__global__ void __launch_bounds__(256) flash_wmma(const float* __restrict__ Q,
    const float* __restrict__ Kb, const float* __restrict__ V,
    float* __restrict__ O) {
  extern __shared__ __nv_bfloat16 smb[];
  __nv_bfloat16* Qh = smb;                 // 64*264
  __nv_bfloat16* Ql = Qh + 16896;
  __nv_bfloat16* KVh = Ql + 16896;
  __nv_bfloat16* KVl = KVh + 16896;
  float* Sbuf = (float*)(smb + 67584);     // 64*72 fp32
  __nv_bfloat16* Ph = (__nv_bfloat16*)(Sbuf + 4608);  // 64*72
  __nv_bfloat16* Pl = Ph + 4608;
  float* Ms = (float*)(Pl + 4608);
  float* Ls = Ms + 64;
  float* Ss = Ls + 64;

  int tid = threadIdx.x, warp = tid >> 5;
  int wm = warp & 1, wn = warp >> 1;       // 2 x 4 warp grid for 64x64 GEMMs
  int rg = tid >> 6, cb = tid & 63;        // O ownership: rows rg*16..+16, col cb
  int b = blockIdx.y >> 2, h = blockIdx.y & 3;
  size_t base = (size_t)b * (2048 * 1024) + h * HDIM;
  int q0 = blockIdx.x * 64;

  // stage Q tile as hi/lo bf16
#pragma unroll
  for (int rep = 0; rep < 16; rep++) {
    int e = rep * 1024 + tid * 4;
    int row = e >> 8, d = e & 255;
    float4 v = *(const float4*)&Q[base + (size_t)(q0 + row) * DIM + d];
    stage4(v, Qh, Ql, row * 264 + d);
  }
  if (tid < 64) { Ms[tid] = -INFINITY; Ls[tid] = 0.f; }
  float o[64];
#pragma unroll
  for (int i = 0; i < 64; i++) o[i] = 0.f;

  for (int kt = 0; kt <= (int)blockIdx.x; kt++) {
    // stage K tile (prev iteration fully consumed KV; see syncs below)
#pragma unroll
    for (int rep = 0; rep < 16; rep++) {
      int e = rep * 1024 + tid * 4;
      int row = e >> 8, d = e & 255;
      float4 v = *(const float4*)&Kb[base + (size_t)(kt * 64 + row) * DIM + d];
      stage4(v, KVh, KVl, row * 264 + d);
    }
    __syncthreads();

    // S = Q K^T (3-pass split). warp tile: rows wm*32 (2 frags), cols wn*16.
    {
      wmma::fragment<wmma::accumulator, 16, 16, 16, float> accS[2];
      wmma::fill_fragment(accS[0], 0.f);
      wmma::fill_fragment(accS[1], 0.f);
#pragma unroll
      for (int d0 = 0; d0 < 256; d0 += 16) {
        wmma::fragment<wmma::matrix_b, 16, 16, 16, __nv_bfloat16, wmma::col_major> kh, kl;
        wmma::load_matrix_sync(kh, KVh + (wn * 16) * 264 + d0, 264);
        wmma::load_matrix_sync(kl, KVl + (wn * 16) * 264 + d0, 264);
#pragma unroll
        for (int mi = 0; mi < 2; mi++) {
          wmma::fragment<wmma::matrix_a, 16, 16, 16, __nv_bfloat16, wmma::row_major> qh, ql;
          wmma::load_matrix_sync(qh, Qh + (wm * 32 + mi * 16) * 264 + d0, 264);
          wmma::load_matrix_sync(ql, Ql + (wm * 32 + mi * 16) * 264 + d0, 264);
          wmma::mma_sync(accS[mi], qh, kh, accS[mi]);
          wmma::mma_sync(accS[mi], qh, kl, accS[mi]);
          wmma::mma_sync(accS[mi], ql, kh, accS[mi]);
        }
      }
#pragma unroll
      for (int mi = 0; mi < 2; mi++)
        wmma::store_matrix_sync(Sbuf + (wm * 32 + mi * 16) * 72 + wn * 16,
                                accS[mi], 72, wmma::mem_row_major);
    }
    __syncthreads();

    // stage V into the KV buffer (K fully consumed), all threads
#pragma unroll
    for (int rep = 0; rep < 16; rep++) {
      int e = rep * 1024 + tid * 4;
      int row = e >> 8, d = e & 255;
      float4 v = *(const float4*)&V[base + (size_t)(kt * 64 + row) * DIM + d];
      stage4(v, KVh, KVl, row * 264 + d);
    }
    // online softmax per row (threads 0..63), emit P as hi/lo bf16
    if (tid < 64) {
      int i = tid;
      int jmax = min(64, q0 + i - kt * 64 + 1);
      float mx = Ms[i];
      for (int j = 0; j < jmax; j++) mx = fmaxf(mx, Sbuf[i * 72 + j]);
      float scale = __expf(Ms[i] - mx);
      float sum = 0.f;
      for (int j = 0; j < 64; j++) {
        float p = (j < jmax) ? __expf(Sbuf[i * 72 + j] - mx) : 0.f;
        cvt_split(p, Ph, Pl, i * 72 + j);
        sum += p;
      }
      Ls[i] = Ls[i] * scale + sum;
      Ms[i] = mx;
      Ss[i] = scale;
    }
    __syncthreads();

    // rescale O by row scale
#pragma unroll
    for (int q = 0; q < 4; q++)
#pragma unroll
      for (int i = 0; i < 16; i++) o[q * 16 + i] *= Ss[rg * 16 + i];

    // O += P V in four 64-column chunks, staged through Sbuf
    for (int q = 0; q < 4; q++) {
      wmma::fragment<wmma::accumulator, 16, 16, 16, float> accO[2];
      wmma::fill_fragment(accO[0], 0.f);
      wmma::fill_fragment(accO[1], 0.f);
#pragma unroll
      for (int k0 = 0; k0 < 64; k0 += 16) {
        wmma::fragment<wmma::matrix_b, 16, 16, 16, __nv_bfloat16, wmma::row_major> vh, vl;
        wmma::load_matrix_sync(vh, KVh + k0 * 264 + q * 64 + wn * 16, 264);
        wmma::load_matrix_sync(vl, KVl + k0 * 264 + q * 64 + wn * 16, 264);
#pragma unroll
        for (int mi = 0; mi < 2; mi++) {
          wmma::fragment<wmma::matrix_a, 16, 16, 16, __nv_bfloat16, wmma::row_major> ph, pl;
          wmma::load_matrix_sync(ph, Ph + (wm * 32 + mi * 16) * 72 + k0, 72);
          wmma::load_matrix_sync(pl, Pl + (wm * 32 + mi * 16) * 72 + k0, 72);
          wmma::mma_sync(accO[mi], ph, vh, accO[mi]);
          wmma::mma_sync(accO[mi], ph, vl, accO[mi]);
          wmma::mma_sync(accO[mi], pl, vh, accO[mi]);
        }
      }
#pragma unroll
      for (int mi = 0; mi < 2; mi++)
        wmma::store_matrix_sync(Sbuf + (wm * 32 + mi * 16) * 72 + wn * 16,
                                accO[mi], 72, wmma::mem_row_major);
      __syncthreads();
#pragma unroll
      for (int i = 0; i < 16; i++)
        o[q * 16 + i] += Sbuf[(rg * 16 + i) * 72 + cb];
      __syncthreads();
    }
  }

  // finalize: divide by L, write out
#pragma unroll
  for (int q = 0; q < 4; q++)
#pragma unroll
    for (int i = 0; i < 16; i++) {
      int row = rg * 16 + i;
      O[base + (size_t)(q0 + row) * DIM + q * 64 + cb] = o[q * 16 + i] / Ls[row];
    }
}

// ---------------------------------------------------------------------------
__global__ void __launch_bounds__(256) den_kernel(const float* __restrict__ Q,
    const float* __restrict__ Kb, const float* __restrict__ z,
    float* __restrict__ denQ, float* __restrict__ denK) {
  __shared__ float sq[256], sk[256];
  int r = blockIdx.x, tid = threadIdx.x;
  int h = tid >> 6, dd = (tid & 63) << 2;
  float4 zv = *(const float4*)&z[h * HDIM + dd];
  float4 qv = *(const float4*)&Q[(size_t)r * DIM + h * HDIM + dd];
  float4 kv = *(const float4*)&Kb[(size_t)r * DIM + h * HDIM + dd];
  sq[tid] = elu1(qv.x)*zv.x + elu1(qv.y)*zv.y + elu1(qv.z)*zv.z + elu1(qv.w)*zv.w;
  sk[tid] = elu1(kv.x)*zv.x + elu1(kv.y)*zv.y + elu1(kv.z)*zv.z + elu1(kv.w)*zv.w;
  __syncthreads();
  if (tid < 8) {
    int hh = tid & 3;
    const float* buf = (tid < 4) ? sq : sk;
    float s = 0.f;
    for (int t = 0; t < 64; t++) s += buf[hh * 64 + t];
    if (tid < 4) denQ[r * 4 + hh] = s; else denK[r * 4 + hh] = s;
  }
}

__global__ void __launch_bounds__(256) u_update(float* __restrict__ V,
    const float* __restrict__ NUM, const float* __restrict__ denK) {
  int idx = blockIdx.x * 256 + threadIdx.x;
  int e = idx << 2;
  int r = e >> 10, h = (e >> 8) & 3;
  float inv = 1.f / (denK[r * 4 + h] + 1e-6f);
  float4 n = *(const float4*)&NUM[e];
  float4 v = *(float4*)&V[e];
  v.x -= n.x * inv; v.y -= n.y * inv; v.z -= n.z * inv; v.w -= n.w * inv;
  *(float4*)&V[e] = v;
}

__global__ void __launch_bounds__(256) blend_kernel(float* __restrict__ NUM,
    const float* __restrict__ ATTN, const float* __restrict__ denQ,
    const float* __restrict__ betas) {
  int idx = blockIdx.x * 256 + threadIdx.x;
  int e = idx << 2;
  int r = e >> 10, h = (e >> 8) & 3;
  float g = 1.f / (1.f + __expf(-betas[h]));
  float inv = g / (denQ[r * 4 + h] + 1e-6f);
  float om = 1.f - g;
  float4 n = *(float4*)&NUM[e];
  float4 a = *(const float4*)&ATTN[e];
  n.x = n.x * inv + om * a.x;
  n.y = n.y * inv + om * a.y;
  n.z = n.z * inv + om * a.z;
  n.w = n.w * inv + om * a.w;
  *(float4*)&NUM[e] = n;
}

__global__ void __launch_bounds__(256) zsum_kernel(const float* __restrict__ Kb,
    const float* __restrict__ z, float* __restrict__ outz) {
  __shared__ float red[256];
  int tid = threadIdx.x;
  int col = blockIdx.x * 64 + (tid & 63);
  int rl = tid >> 6;
  float s = 0.f;
  for (int r = rl; r < R_ROWS; r += 4) s += elu1(Kb[(size_t)r * DIM + col]);
  red[tid] = s;
  __syncthreads();
  if (tid < 64) {
    int c = blockIdx.x * 64 + tid;
    outz[c] = z[c] + 0.25f * (red[tid] + red[tid + 64] + red[tid + 128] + red[tid + 192]);
  }
}

// ---------------------------------------------------------------------------
extern "C" void kernel_launch(void* const* d_in, const int* in_sizes, int n_in,
                              void* d_out, int out_size) {
  const float* X     = (const float*)d_in[0];
  const float* Wq    = (const float*)d_in[1];
  const float* Wk    = (const float*)d_in[2];
  const float* Wv    = (const float*)d_in[3];
  const float* Wo    = (const float*)d_in[4];
  const float* bo    = (const float*)d_in[5];
  const float* betas = (const float*)d_in[6];
  const float* memin = (const float*)d_in[7];
  const float* zin   = (const float*)d_in[8];
  float* out     = (float*)d_out;
  float* out_mem = out + 8388608;   // [4,256,256]
  float* out_z   = out + 8650752;   // [4,256,1]

  float *pQ, *pK, *pV, *pA, *pN, *pDQ, *pDK;
  cudaGetSymbolAddress((void**)&pQ,  g_Q);
  cudaGetSymbolAddress((void**)&pK,  g_K);
  cudaGetSymbolAddress((void**)&pV,  g_V);
  cudaGetSymbolAddress((void**)&pA,  g_ATTN);
  cudaGetSymbolAddress((void**)&pN,  g_NUM);
  cudaGetSymbolAddress((void**)&pDQ, g_DENQ);
  cudaGetSymbolAddress((void**)&pDK, g_DENK);

  dim3 gmma(DIM / 64, R_ROWS / 128);  // (16, 64)
  gemm_tn_wmma<<<gmma, 256>>>(X, Wq, nullptr, pQ, R_ROWS, DIM, DIM);
  gemm_tn_wmma<<<gmma, 256>>>(X, Wk, nullptr, pK, R_ROWS, DIM, DIM);
  gemm_tn_wmma<<<gmma, 256>>>(X, Wv, nullptr, pV, R_ROWS, DIM, DIM);

  // Causal attention (WMMA)
  cudaFuncSetAttribute(flash_wmma, cudaFuncAttributeMaxDynamicSharedMemorySize, FLW_SMEM);
  flash_wmma<<<dim3(32, 16), 256, FLW_SMEM>>>(pQ, pK, pV, pA);

  // delta-rule path
  gemm_nn_elu<<<dim3(4, 128, 4), 256>>>(pK, memin, pN);
  den_kernel<<<R_ROWS, 256>>>(pQ, pK, zin, pDQ, pDK);
  u_update<<<R_ROWS, 256>>>(pV, pN, pDK);

  // state updates
  gemm_atb<<<dim3(4, 4, 4), 256>>>(pK, pV, memin, out_mem);
  zsum_kernel<<<16, 256>>>(pK, zin, out_z);

  // memory read path + blend
  gemm_nn_elu<<<dim3(4, 128, 4), 256>>>(pQ, memin, pN);
  blend_kernel<<<R_ROWS, 256>>>(pN, pA, pDQ, betas);

  // output projection (+bias)
  gemm_tn_wmma<<<gmma, 256>>>(pN, Wo, bo, out, R_ROWS, DIM, DIM);
}